// round 17
// baseline (speedup 1.0000x reference)
#include <cuda_runtime.h>

// ChronoRotationTransflormation: per-row normalized complex inner product.
// Inputs: head_real, head_imag, rel_real, rel_imag, tail_real, tail_imag
// all float32 [8192, 2048]. Output: float32 [8192].
//
// R16: 256-bit loads (sm_100+ ld.global.v8.f32). CTA-per-row, 256 threads,
// ONE LDG.256 per thread per array (8 floats x 256 threads = 2048 = D).
// Halves LDG dispatch count vs the LDG.128 champion at identical traffic,
// giving the LSU/L1tex pipeline more issue slack. evict_first (streaming).

#define D 2048
#define THREADS 256         // 8 floats per thread
#define WARPS (THREADS / 32)

struct f8 { float v[8]; };

__device__ __forceinline__ f8 ldg256_stream(const float* p)
{
    f8 r;
    asm volatile(
        "ld.global.nc.L2::evict_first.v8.f32 "
        "{%0, %1, %2, %3, %4, %5, %6, %7}, [%8];"
        : "=f"(r.v[0]), "=f"(r.v[1]), "=f"(r.v[2]), "=f"(r.v[3]),
          "=f"(r.v[4]), "=f"(r.v[5]), "=f"(r.v[6]), "=f"(r.v[7])
        : "l"(p));
    return r;
}

__global__ __launch_bounds__(THREADS)
void chrono_rot_kernel(const float* __restrict__ hr,
                       const float* __restrict__ hi,
                       const float* __restrict__ rr,
                       const float* __restrict__ ri,
                       const float* __restrict__ tr,
                       const float* __restrict__ ti,
                       float* __restrict__ out)
{
    const long long off = (long long)blockIdx.x * D + threadIdx.x * 8;

    // 6 independent 256-bit streaming loads, front-batched.
    const f8 HR = ldg256_stream(hr + off);
    const f8 HI = ldg256_stream(hi + off);
    const f8 RR = ldg256_stream(rr + off);
    const f8 RI = ldg256_stream(ri + off);
    const f8 TR = ldg256_stream(tr + off);
    const f8 TI = ldg256_stream(ti + off);

    float ab = 0.f, aa = 0.f, bb = 0.f;
    #pragma unroll
    for (int k = 0; k < 8; ++k) {
        const float h_r = HR.v[k], h_i = HI.v[k];
        const float r_r = RR.v[k], r_i = RI.v[k];
        const float t_r = TR.v[k], t_i = TI.v[k];
        const float rot_r = h_r * r_r - h_i * r_i;
        const float rot_i = -(h_i * r_r + h_r * r_i);
        ab = fmaf(rot_r, t_r, fmaf(rot_i, t_i, ab));
        // |rot|^2 = (h_r^2 + h_i^2) * (r_r^2 + r_i^2)
        const float h2 = fmaf(h_r, h_r, h_i * h_i);
        const float r2 = fmaf(r_r, r_r, r_i * r_i);
        aa = fmaf(h2, r2, aa);
        bb = fmaf(t_r, t_r, fmaf(t_i, t_i, bb));
    }

    // Warp butterfly reduction.
    #pragma unroll
    for (int offs = 16; offs > 0; offs >>= 1) {
        ab += __shfl_xor_sync(0xFFFFFFFFu, ab, offs);
        aa += __shfl_xor_sync(0xFFFFFFFFu, aa, offs);
        bb += __shfl_xor_sync(0xFFFFFFFFu, bb, offs);
    }

    __shared__ float s_ab[WARPS], s_aa[WARPS], s_bb[WARPS];
    const int wid = threadIdx.x >> 5;
    const int lid = threadIdx.x & 31;
    if (lid == 0) {
        s_ab[wid] = ab;
        s_aa[wid] = aa;
        s_bb[wid] = bb;
    }
    __syncthreads();

    // Final reduction by warp 0: 8 partials in lanes 0..7.
    if (wid == 0) {
        float tab = (lid < WARPS) ? s_ab[lid] : 0.f;
        float taa = (lid < WARPS) ? s_aa[lid] : 0.f;
        float tbb = (lid < WARPS) ? s_bb[lid] : 0.f;
        #pragma unroll
        for (int offs = 4; offs > 0; offs >>= 1) {
            tab += __shfl_xor_sync(0xFFFFFFFFu, tab, offs);
            taa += __shfl_xor_sync(0xFFFFFFFFu, taa, offs);
            tbb += __shfl_xor_sync(0xFFFFFFFFu, tbb, offs);
        }
        if (lid == 0)
            out[blockIdx.x] = tab / sqrtf(taa * tbb);
    }
}

extern "C" void kernel_launch(void* const* d_in, const int* in_sizes, int n_in,
                              void* d_out, int out_size)
{
    const float* hr = (const float*)d_in[0];
    const float* hi = (const float*)d_in[1];
    const float* rr = (const float*)d_in[2];
    const float* ri = (const float*)d_in[3];
    const float* tr = (const float*)d_in[4];
    const float* ti = (const float*)d_in[5];
    float* out = (float*)d_out;

    const int rows = out_size;  // 8192
    chrono_rot_kernel<<<rows, THREADS>>>(hr, hi, rr, ri, tr, ti, out);
}